// round 16
// baseline (speedup 1.0000x reference)
#include <cuda_runtime.h>
#include <cuda_fp16.h>
#include <cstdint>

#define B_  4
#define T_  512
#define G_  129
#define F_  96
#define O_  96

#define HM  256                         // window rows
#define HROWS 258                       // + halo
#define NWIN 8
#define XROWB 208                       // bytes per fp16 x row: 192 data + 16 pad
#define XB_BYTES (HROWS * XROWB)        // 53664 per buffer

#define WBLKB 3072                      // per (kk,step) W block: 2 planes x 32 slots x 48B
#define WS_BYTES (18 * WBLKB)           // 55296

#define SM_X0  WS_BYTES
#define SMEM_TOTAL (WS_BYTES + 2 * XB_BYTES)   // 162624

#define NTHREADS 384                    // 8 consumer warps + 4 producer warps

__device__ __forceinline__ uint32_t pack_f16x2(float lo, float hi) {
    uint32_t r;
    asm("cvt.rn.f16x2.f32 %0, %2, %1;" : "=r"(r) : "f"(lo), "f"(hi));
    return r;
}
__device__ __forceinline__ void mma_f16(float c[4], uint32_t a0, uint32_t a1, uint32_t a2,
                                        uint32_t a3, uint32_t b0, uint32_t b1) {
    asm volatile(
        "mma.sync.aligned.m16n8k16.row.col.f32.f16.f16.f32 "
        "{%0,%1,%2,%3}, {%4,%5,%6,%7}, {%8,%9}, {%0,%1,%2,%3};"
        : "+f"(c[0]), "+f"(c[1]), "+f"(c[2]), "+f"(c[3])
        : "r"(a0), "r"(a1), "r"(a2), "r"(a3), "r"(b0), "r"(b1));
}

// producer fill: window h (fp32 global -> fp16 smem, direct, predicated zero at batch edges)
__device__ __forceinline__ void fill_window(char* xd, const float* xg, int h, int tidp) {
    const int bb = h >> 1, t0 = (h & 1) * HM;
    const float* xgb = xg + (size_t)bb * (T_ * G_ * F_);
    #pragma unroll 2
    for (int q = tidp; q < HROWS * 12; q += 128) {
        int p = q / 12, c = q - p * 12;          // c: 8-float chunk
        int t = t0 - 1 + p;
        float4 lo = make_float4(0.f, 0.f, 0.f, 0.f), hi = lo;
        if (t >= 0 && t < T_) {
            const float* src = xgb + (size_t)t * (G_ * F_) + c * 8;
            lo = *(const float4*)(src);
            hi = *(const float4*)(src + 4);
        }
        *(uint4*)(xd + p * XROWB + c * 16) =
            make_uint4(pack_f16x2(lo.x, lo.y), pack_f16x2(lo.z, lo.w),
                       pack_f16x2(hi.x, hi.y), pack_f16x2(hi.z, hi.w));
    }
}

__global__ __launch_bounds__(NTHREADS, 1)
void conv1d_mma_kernel(const float* __restrict__ x,
                       const float* __restrict__ w,
                       const float* __restrict__ bias,
                       float* __restrict__ out)
{
    extern __shared__ char smc[];
    char* ws_b = smc;                                   // W fp16, slot layout
    const int tid = threadIdx.x, wid = tid >> 5, lane = tid & 31;
    const int g = blockIdx.x;
    const bool producer = (wid >= 8);
    const int tidp = tid & 127;                         // producer thread idx
    const int wm = wid & 3, wn = (wid >> 2) & 1;        // consumers: 4 M-warps x 2 N-warps
    const int lane4 = lane >> 2, lc = lane & 3;

    char* xbuf[2] = { smc + SM_X0, smc + SM_X0 + XB_BYTES };
    const float* xg = x + (size_t)g * F_;

    // ---- W[g] -> smem fp16 (rn), slot layout, once per CTA (all threads)
    {
        const float4* wg4 = (const float4*)(w + (size_t)g * (O_ * F_ * 3));
        for (int q = tid; q < (O_ * F_ * 3) / 4; q += NTHREADS) {
            float4 v = wg4[q];
            int e = q * 4;
            int o = e / (F_ * 3);
            int rem = e - o * (F_ * 3);                  // o fixed across the 4
            int nblk = o >> 3, orow = o & 7;
            int pos = (nblk < 4) ? nblk : (nblk < 6 ? nblk + 4 : (nblk < 10 ? nblk - 2 : nblk));
            const float* vf = (const float*)&v;
            #pragma unroll
            for (int j = 0; j < 4; ++j) {
                int rr = rem + j;
                int f = rr / 3, kk = rr - 3 * f;
                int s = f >> 4, fh = f & 15;
                int plane = fh >> 3, kp = (fh & 7) >> 1, klo = fh & 1;
                int slot = orow * 4 + kp;
                int off = (kk * 6 + s) * WBLKB + plane * 1536 + slot * 48 + pos * 4 + klo * 2;
                *(__half*)(ws_b + off) = __float2half_rn(vf[j]);
            }
        }
    }

    float bias0[6], bias1[6];

    // ---- prologue: producers fill window 0; consumers load bias
    if (producer) {
        fill_window(xbuf[0], xg, 0, tidp);
    } else {
        const float* bg = bias + g * O_ + wn * 48 + 2 * lc;
        #pragma unroll
        for (int jn = 0; jn < 6; ++jn) { bias0[jn] = bg[jn * 8]; bias1[jn] = bg[jn * 8 + 1]; }
    }
    __syncthreads();

    const char* pbl = ws_b + lane * 48;

    // ---- 8 slots: consumers compute window i; producers fill window i+1
    for (int i = 0; i < NWIN; ++i) {
        if (producer) {
            if (i < NWIN - 1) fill_window(xbuf[(i + 1) & 1], xg, i + 1, tidp);
        } else {
            const char* xb_b = xbuf[i & 1];
            const char* paw = xb_b + (wm * 64 + lane4) * XROWB + lc * 4;

            float acc[4][6][4];
            #pragma unroll
            for (int jn = 0; jn < 6; ++jn) {
                #pragma unroll
                for (int mb = 0; mb < 4; ++mb) {
                    acc[mb][jn][0] = bias0[jn]; acc[mb][jn][1] = bias1[jn];
                    acc[mb][jn][2] = bias0[jn]; acc[mb][jn][3] = bias1[jn];
                }
            }

            #pragma unroll
            for (int kk = 0; kk < 3; ++kk) {
                #pragma unroll
                for (int s = 0; s < 6; ++s) {
                    const char* pbs = pbl + (kk * 6 + s) * WBLKB;
                    uint4 q0 = *(const uint4*)(pbs + wn * 16);
                    uint2 q1 = *(const uint2*)(pbs + 32 + wn * 8);
                    uint4 q2 = *(const uint4*)(pbs + 1536 + wn * 16);
                    uint2 q3 = *(const uint2*)(pbs + 1536 + 32 + wn * 8);
                    uint32_t b0f[6] = { q0.x, q0.y, q0.z, q0.w, q1.x, q1.y };
                    uint32_t b1f[6] = { q2.x, q2.y, q2.z, q2.w, q3.x, q3.y };

                    const char* pam = paw + kk * XROWB + s * 32;
                    #pragma unroll
                    for (int mb = 0; mb < 4; ++mb) {
                        const char* pm = pam + mb * (16 * XROWB);
                        uint32_t a0 = *(const uint32_t*)(pm);
                        uint32_t a2 = *(const uint32_t*)(pm + 16);
                        uint32_t a1 = *(const uint32_t*)(pm + 8 * XROWB);
                        uint32_t a3 = *(const uint32_t*)(pm + 8 * XROWB + 16);
                        #pragma unroll
                        for (int jn = 0; jn < 6; ++jn)
                            mma_f16(acc[mb][jn], a0, a1, a2, a3, b0f[jn], b1f[jn]);
                    }
                }
            }

            // store window i
            const int colb = wn * 48 + 2 * lc;
            #pragma unroll
            for (int mb = 0; mb < 4; ++mb) {
                int rbase = i * HM + wm * 64 + mb * 16 + lane4;
                #pragma unroll
                for (int hh = 0; hh < 2; ++hh) {
                    size_t gm = (size_t)(rbase + hh * 8);
                    float* op = out + (gm * G_ + g) * O_ + colb;
                    #pragma unroll
                    for (int jn = 0; jn < 6; ++jn)
                        *(float2*)(op + jn * 8) =
                            make_float2(acc[mb][jn][2 * hh], acc[mb][jn][2 * hh + 1]);
                }
            }
        }
        __syncthreads();
    }
}

extern "C" void kernel_launch(void* const* d_in, const int* in_sizes, int n_in,
                              void* d_out, int out_size)
{
    const float* x    = (const float*)d_in[0];
    const float* wgt  = (const float*)d_in[1];
    const float* bias = (const float*)d_in[2];
    float* out        = (float*)d_out;

    cudaFuncSetAttribute(conv1d_mma_kernel,
                         cudaFuncAttributeMaxDynamicSharedMemorySize, SMEM_TOTAL);

    conv1d_mma_kernel<<<G_, NTHREADS, SMEM_TOTAL>>>(x, wgt, bias, out);
}